// round 5
// baseline (speedup 1.0000x reference)
#include <cuda_runtime.h>
#include <math.h>

#define CIN  64
#define COUT 128
#define HH   512
#define WW   512

__device__ float  d_y[COUT * HH * WW];     // conv output      (128 MB)
__device__ float2 d_spec[COUT * HH * WW];  // working spectrum (256 MB)

// ===========================================================================
// Packed fp32x2 helpers (sm_103a dual-FMA path)
// ===========================================================================
__device__ __forceinline__ unsigned long long pack2(float a, float b) {
    unsigned long long r;
    asm("mov.b64 %0, {%1, %2};" : "=l"(r) : "f"(a), "f"(b));
    return r;
}
__device__ __forceinline__ void unpack2(unsigned long long v, float& a, float& b) {
    asm("mov.b64 {%0, %1}, %2;" : "=f"(a), "=f"(b) : "l"(v));
}
__device__ __forceinline__ void fma2(unsigned long long& acc,
                                     unsigned long long x, unsigned long long w) {
    asm("fma.rn.f32x2 %0, %1, %2, %0;" : "+l"(acc) : "l"(x), "l"(w));
}

// ===========================================================================
// Conv 3x3 (cross-correlation, same padding), packed fp32x2 FMA.
// Block tile: 4 co x 16 h x 128 w. Thread: 4 co x 8 w px (16 fp32x2 accs).
// Weights for the block preloaded once as duplicated u64 pairs (LDS.64 bcast).
// Double-buffered x tile with register prefetch; 1 barrier per ci.
// ===========================================================================
#define CO_T 4
#define HT   16
#define WTI  128
#define XP   132                      // padded row pitch (floats), 16B-aligned
#define XELEM ((HT + 2) * (WTI + 2))  // 2340

__global__ __launch_bounds__(256, 2) void conv3x3_kernel(
    const float* __restrict__ x, const float* __restrict__ wgt,
    const float* __restrict__ bias)
{
    __shared__ unsigned long long swd[CO_T * CIN * 9];   // 18.4 KB
    __shared__ float sx[2][HT + 2][XP];                  // 19.0 KB

    const int tid = threadIdx.x;
    const int tx  = tid & 15;     // 16 groups along W, 8 px each
    const int ty  = tid >> 4;     // 16 rows
    const int w0  = blockIdx.x * WTI;
    const int h0  = blockIdx.y * HT;
    const int co0 = blockIdx.z * CO_T;

    // ---- one-time weight preload (duplicated into both u64 halves) ----
    for (int i = tid; i < CO_T * CIN * 9; i += 256) {
        int c   = i / (CIN * 9);
        int rem = i - c * (CIN * 9);
        float w = wgt[(co0 + c) * (CIN * 9) + rem];
        swd[i] = pack2(w, w);
    }

    // ---- initial x tile (ci = 0) ----
    for (int i = tid; i < XELEM; i += 256) {
        int r = i / (WTI + 2), c = i - r * (WTI + 2);
        int hh = h0 + r - 1, ww = w0 + c - 1;
        float v = 0.f;
        if (hh >= 0 && hh < HH && ww >= 0 && ww < WW)
            v = x[hh * WW + ww];
        sx[0][r][c] = v;
    }
    __syncthreads();

    unsigned long long acc[CO_T][4];
#pragma unroll
    for (int c = 0; c < CO_T; c++)
#pragma unroll
        for (int q = 0; q < 4; q++) acc[c][q] = 0ull;

    for (int ci = 0; ci < CIN; ci++) {
        // ---- prefetch next channel tile into registers ----
        float pf[10];
        if (ci + 1 < CIN) {
            const float* xn = x + (ci + 1) * HH * WW;
#pragma unroll
            for (int j = 0; j < 10; j++) {
                int i = tid + 256 * j;
                float v = 0.f;
                if (i < XELEM) {
                    int r = i / (WTI + 2), c = i - r * (WTI + 2);
                    int hh = h0 + r - 1, ww = w0 + c - 1;
                    if (hh >= 0 && hh < HH && ww >= 0 && ww < WW)
                        v = xn[hh * WW + ww];
                }
                pf[j] = v;
            }
        }

        // ---- compute from current buffer, kh-inner to cap live registers ----
        const int b = ci & 1;
        const unsigned long long* wrow = &swd[ci * 9];
#pragma unroll
        for (int kh = 0; kh < 3; kh++) {
            const float* rowp = &sx[b][ty + kh][tx * 8];
            // 10 floats as aligned vector loads: 2x LDS.128 + 1x LDS.64
            float4 a4 = *(const float4*)(rowp);
            float4 b4 = *(const float4*)(rowp + 4);
            float2 c2 = *(const float2*)(rowp + 8);
            unsigned long long xp[9];
            xp[0] = pack2(a4.x, a4.y);
            xp[1] = pack2(a4.y, a4.z);
            xp[2] = pack2(a4.z, a4.w);
            xp[3] = pack2(a4.w, b4.x);
            xp[4] = pack2(b4.x, b4.y);
            xp[5] = pack2(b4.y, b4.z);
            xp[6] = pack2(b4.z, b4.w);
            xp[7] = pack2(b4.w, c2.x);
            xp[8] = pack2(c2.x, c2.y);
#pragma unroll
            for (int c = 0; c < CO_T; c++) {
                const unsigned long long* wc = wrow + c * (CIN * 9) + kh * 3;
#pragma unroll
                for (int kw = 0; kw < 3; kw++) {
                    unsigned long long w2 = wc[kw];
#pragma unroll
                    for (int q = 0; q < 4; q++)
                        fma2(acc[c][q], xp[2 * q + kw], w2);
                }
            }
        }

        // ---- store prefetched tile into the other buffer ----
        if (ci + 1 < CIN) {
            const int nb = (ci + 1) & 1;
#pragma unroll
            for (int j = 0; j < 10; j++) {
                int i = tid + 256 * j;
                if (i < XELEM) {
                    int r = i / (WTI + 2), c = i - r * (WTI + 2);
                    sx[nb][r][c] = pf[j];
                }
            }
        }
        __syncthreads();
    }

#pragma unroll
    for (int c = 0; c < CO_T; c++) {
        float bv = bias[co0 + c];
        float p0, p1, p2, p3, p4, p5, p6, p7;
        unpack2(acc[c][0], p0, p1);
        unpack2(acc[c][1], p2, p3);
        unpack2(acc[c][2], p4, p5);
        unpack2(acc[c][3], p6, p7);
        float* orow = &d_y[((co0 + c) * HH + (h0 + ty)) * WW + w0 + tx * 8];
        *(float4*)(orow)     = make_float4(p0 + bv, p1 + bv, p2 + bv, p3 + bv);
        *(float4*)(orow + 4) = make_float4(p4 + bv, p5 + bv, p6 + bv, p7 + bv);
    }
}

// ===========================================================================
// Register-resident 512-pt FFT: per-lane FFT-16 (regs) x cross-lane FFT-32
// (shfl). Decomposition n = n1 + 32*n2 (lane n1, reg n2);
// forward output X[k2 + 16*k1] at (lane k1, reg k2). Inverse is the mirror.
// ===========================================================================
template<int INV>
__device__ __forceinline__ void fft16_reg(float2 v[16])
{
    float2 t;
    t = v[1];  v[1]  = v[8];  v[8]  = t;
    t = v[2];  v[2]  = v[4];  v[4]  = t;
    t = v[3];  v[3]  = v[12]; v[12] = t;
    t = v[5];  v[5]  = v[10]; v[10] = t;
    t = v[7];  v[7]  = v[14]; v[14] = t;
    t = v[11]; v[11] = v[13]; v[13] = t;

    const float CC[8] = { 1.f,  0.92387953251128674f,  0.70710678118654752f,
                          0.38268343236508977f, 0.f, -0.38268343236508977f,
                         -0.70710678118654752f, -0.92387953251128674f };
    const float SS[8] = { 0.f,  0.38268343236508977f,  0.70710678118654752f,
                          0.92387953251128674f, 1.f,  0.92387953251128674f,
                          0.70710678118654752f,  0.38268343236508977f };
#pragma unroll
    for (int st = 1; st <= 4; st++) {
        const int half = 1 << (st - 1);
#pragma unroll
        for (int j = 0; j < 8; j++) {
            const int pos = j & (half - 1);
            const int i0  = ((j >> (st - 1)) << st) | pos;
            const int i1  = i0 + half;
            const int tj  = pos << (4 - st);
            const float wr = CC[tj];
            const float wi = INV ? SS[tj] : -SS[tj];
            float br = v[i1].x * wr - v[i1].y * wi;
            float bi = v[i1].x * wi + v[i1].y * wr;
            v[i1].x = v[i0].x - br; v[i1].y = v[i0].y - bi;
            v[i0].x += br;          v[i0].y += bi;
        }
    }
}

template<int INV>
__device__ __forceinline__ void fft32_xlane(float2 v[16], int lane)
{
    const unsigned m = 0xffffffffu;
    int rl = __brev(lane) >> 27;
#pragma unroll
    for (int r = 0; r < 16; r++) {
        v[r].x = __shfl_sync(m, v[r].x, rl);
        v[r].y = __shfl_sync(m, v[r].y, rl);
    }
#pragma unroll
    for (int st = 1; st <= 5; st++) {
        const int half = 1 << (st - 1);
        float ang = (INV ? 3.14159265358979323f : -3.14159265358979323f)
                    * (float)(lane & (half - 1)) / (float)half;
        float wi, wr;
        __sincosf(ang, &wi, &wr);
        const float sgn = (lane & half) ? -1.f : 1.f;
        const bool hi = (lane & half) != 0;
#pragma unroll
        for (int r = 0; r < 16; r++) {
            float px = __shfl_xor_sync(m, v[r].x, half);
            float py = __shfl_xor_sync(m, v[r].y, half);
            float bx = hi ? v[r].x : px;
            float by = hi ? v[r].y : py;
            float ax = hi ? px : v[r].x;
            float ay = hi ? py : v[r].y;
            float tx = bx * wr - by * wi;
            float ty = bx * wi + by * wr;
            v[r].x = fmaf(sgn, tx, ax);
            v[r].y = fmaf(sgn, ty, ay);
        }
    }
}

template<int INV>
__device__ __forceinline__ void twiddle512(float2 v[16], int lane)
{
    float ang = (INV ? 6.28318530717958648f : -6.28318530717958648f)
                * (float)lane / 512.f;
    float s, c;
    __sincosf(ang, &s, &c);
    float wr = 1.f, wi = 0.f;
#pragma unroll
    for (int r = 1; r < 16; r++) {
        float nwr = wr * c - wi * s;
        float nwi = wr * s + wi * c;
        wr = nwr; wi = nwi;
        float xr = v[r].x, xi = v[r].y;
        v[r].x = xr * wr - xi * wi;
        v[r].y = xr * wi + xi * wr;
    }
}

__device__ __forceinline__ void fft512_fwd(float2 v[16], int lane)
{
    fft16_reg<0>(v);
    twiddle512<0>(v, lane);
    fft32_xlane<0>(v, lane);
}
__device__ __forceinline__ void fft512_inv(float2 v[16], int lane)
{
    fft32_xlane<1>(v, lane);
    twiddle512<1>(v, lane);
    fft16_reg<1>(v);
}

// XOR swizzle for the k-major float2 slab (logical idx = 8*k + c, k<512, c<8)
__device__ __forceinline__ int swz(int idx) { return idx ^ ((idx >> 7) & 15); }

// ===========================================================================
// Pass 1: forward FFT along H. 8 columns/block, warp-per-column.
// ===========================================================================
__global__ __launch_bounds__(256) void fft_cols_fwd()
{
    __shared__ char raw[32768];
    float*  sIn  = (float*)raw;     // [h*9 + c]
    float2* sOut = (float2*)raw;    // swizzled [8k+c]

    const int tid  = threadIdx.x;
    const int lane = tid & 31;
    const int wp   = tid >> 5;
    const int ch   = blockIdx.y;
    const int w0   = blockIdx.x * 8;

    for (int i = tid; i < 4096; i += 256) {
        int h = i >> 3, c = i & 7;
        sIn[h * 9 + c] = d_y[(ch * HH + h) * WW + w0 + c];
    }
    __syncthreads();

    float2 v[16];
#pragma unroll
    for (int r = 0; r < 16; r++)
        v[r] = make_float2(sIn[(lane + 32 * r) * 9 + wp], 0.f);
    __syncthreads();

    fft512_fwd(v, lane);

#pragma unroll
    for (int r = 0; r < 16; r++) {
        int k = r + 16 * lane;
        sOut[swz((k << 3) | wp)] = v[r];
    }
    __syncthreads();

    for (int i = tid; i < 4096; i += 256) {
        int k = i >> 3, c = i & 7;
        d_spec[(ch * HH + k) * WW + w0 + c] = sOut[swz(i)];
    }
}

// ===========================================================================
// Pass 2: fused forward FFT along W, mask*(1/N^2), inverse FFT along W.
// ===========================================================================
__global__ __launch_bounds__(256) void fft_rows_mask(const float* __restrict__ mask)
{
    __shared__ float sm[8][528];

    const int tid  = threadIdx.x;
    const int lane = tid & 31;
    const int wp   = tid >> 5;
    const int ch   = blockIdx.y;
    const int h    = blockIdx.x * 8 + wp;

    float2* row  = &d_spec[(ch * HH + h) * WW];
    const float* mrow = &mask[(ch * HH + h) * WW];

    float2 v[16];
#pragma unroll
    for (int r = 0; r < 16; r++)
        v[r] = row[lane + 32 * r];
#pragma unroll
    for (int t = 0; t < 16; t++) {
        int i = lane + 32 * t;
        sm[wp][i + (i >> 5)] = mrow[i];
    }

    fft512_fwd(v, lane);
    __syncwarp();

    const float sc = 1.0f / (512.0f * 512.0f);
#pragma unroll
    for (int r = 0; r < 16; r++) {
        int k = r + 16 * lane;
        float mv = sm[wp][k + (k >> 5)] * sc;
        v[r].x *= mv; v[r].y *= mv;
    }

    fft512_inv(v, lane);

#pragma unroll
    for (int r = 0; r < 16; r++)
        row[lane + 32 * r] = v[r];
}

// ===========================================================================
// Pass 3: inverse FFT along H, write real part.
// ===========================================================================
__global__ __launch_bounds__(256) void fft_cols_inv(float* __restrict__ out)
{
    __shared__ char raw[32768];
    float2* sIn  = (float2*)raw;
    float*  sOut = (float*)raw;

    const int tid  = threadIdx.x;
    const int lane = tid & 31;
    const int wp   = tid >> 5;
    const int ch   = blockIdx.y;
    const int w0   = blockIdx.x * 8;

    for (int i = tid; i < 4096; i += 256) {
        int k = i >> 3, c = i & 7;
        sIn[swz(i)] = d_spec[(ch * HH + k) * WW + w0 + c];
    }
    __syncthreads();

    float2 v[16];
#pragma unroll
    for (int r = 0; r < 16; r++) {
        int k = r + 16 * lane;
        v[r] = sIn[swz((k << 3) | wp)];
    }
    __syncthreads();

    fft512_inv(v, lane);

#pragma unroll
    for (int r = 0; r < 16; r++)
        sOut[(lane + 32 * r) * 9 + wp] = v[r].x;
    __syncthreads();

    for (int i = tid; i < 4096; i += 256) {
        int hh = i >> 3, c = i & 7;
        out[(ch * HH + hh) * WW + w0 + c] = sOut[hh * 9 + c];
    }
}

// ===========================================================================
extern "C" void kernel_launch(void* const* d_in, const int* in_sizes, int n_in,
                              void* d_out, int out_size)
{
    const float* x    = (const float*)d_in[0];   // (64,512,512)
    const float* wgt  = (const float*)d_in[1];   // (128,64,3,3)
    const float* bias = (const float*)d_in[2];   // (128,)
    const float* mask = (const float*)d_in[3];   // (128,512,512)
    float* out = (float*)d_out;                  // (128,512,512)

    conv3x3_kernel<<<dim3(WW / WTI, HH / HT, COUT / CO_T), 256>>>(x, wgt, bias);
    fft_cols_fwd <<<dim3(WW / 8, COUT), 256>>>();
    fft_rows_mask<<<dim3(HH / 8, COUT), 256>>>(mask);
    fft_cols_inv <<<dim3(WW / 8, COUT), 256>>>(out);
}

// round 8
// speedup vs baseline: 1.7307x; 1.7307x over previous
#include <cuda_runtime.h>
#include <math.h>

#define CIN  64
#define COUT 128
#define HH   512
#define WW   512

__device__ float  d_y[COUT * HH * WW];     // conv output      (128 MB)
__device__ float2 d_spec[COUT * HH * WW];  // working spectrum (256 MB)

// ===========================================================================
// Packed fp32x2 helpers (sm_103a dual-FMA path)
// ===========================================================================
__device__ __forceinline__ unsigned long long pack2(float a, float b) {
    unsigned long long r;
    asm("mov.b64 %0, {%1, %2};" : "=l"(r) : "f"(a), "f"(b));
    return r;
}
__device__ __forceinline__ void unpack2(unsigned long long v, float& a, float& b) {
    asm("mov.b64 {%0, %1}, %2;" : "=f"(a), "=f"(b) : "l"(v));
}
__device__ __forceinline__ void fma2(unsigned long long& acc,
                                     unsigned long long x, unsigned long long w) {
    asm("fma.rn.f32x2 %0, %1, %2, %0;" : "+l"(acc) : "l"(x), "l"(w));
}

// ===========================================================================
// Conv 3x3 (cross-correlation, same padding) with packed fp32x2 FMA.
// Block: 8 co x 16 h x 64 w. Thread: 8 co x 4 w px (2 fp32x2 accumulators).
// Weight smem layout [ci][k][co] as duplicated u64 pairs -> one LDS.128
// broadcast feeds TWO output channels. x rows loaded as float4+float2.
// Double-buffered x tile with register prefetch; 1 barrier per ci.
// ===========================================================================
#define CO_T 8
#define HT   16
#define WT   64
#define XP   68   // padded x row pitch (floats): 272B, 16B-aligned

__global__ __launch_bounds__(256, 2) void conv3x3_kernel(
    const float* __restrict__ x, const float* __restrict__ wgt,
    const float* __restrict__ bias)
{
    __shared__ unsigned long long swd[CIN * 9 * CO_T];   // [ci][k][co], 36.9 KB
    __shared__ float sx[2][HT + 2][XP];                  // 9.8 KB

    const int tid = threadIdx.x;
    const int tx  = tid & 15;    // 16 groups along W, 4 px each
    const int ty  = tid >> 4;    // 16 rows
    const int w0  = blockIdx.x * WT;
    const int h0  = blockIdx.y * HT;
    const int co0 = blockIdx.z * CO_T;

    // ---- one-time weight preload: swd[(ci*9 + k)*8 + c] = dup(w[co0+c][ci][k])
    for (int i = tid; i < CIN * 9 * CO_T; i += 256) {
        int c   = i & 7;
        int kci = i >> 3;          // ci*9 + k
        int ci  = kci / 9;
        int k   = kci - ci * 9;
        float w = wgt[((co0 + c) * CIN + ci) * 9 + k];
        swd[i] = pack2(w, w);
    }

    // ---- initial x tile (ci = 0) ----
    for (int i = tid; i < (HT + 2) * (WT + 2); i += 256) {
        int r = i / (WT + 2), c = i - r * (WT + 2);
        int hh = h0 + r - 1, ww = w0 + c - 1;
        float v = 0.f;
        if (hh >= 0 && hh < HH && ww >= 0 && ww < WW)
            v = x[hh * WW + ww];
        sx[0][r][c] = v;
    }
    __syncthreads();

    unsigned long long acc[CO_T][2];
#pragma unroll
    for (int c = 0; c < CO_T; c++) { acc[c][0] = 0ull; acc[c][1] = 0ull; }

    for (int ci = 0; ci < CIN; ci++) {
        // ---- prefetch next channel tile into registers ----
        float pf[5];
        if (ci + 1 < CIN) {
            const float* xn = x + (ci + 1) * HH * WW;
#pragma unroll
            for (int j = 0; j < 5; j++) {
                int i = tid + 256 * j;
                float v = 0.f;
                if (i < (HT + 2) * (WT + 2)) {
                    int r = i / (WT + 2), c = i - r * (WT + 2);
                    int hh = h0 + r - 1, ww = w0 + c - 1;
                    if (hh >= 0 && hh < HH && ww >= 0 && ww < WW)
                        v = xn[hh * WW + ww];
                }
                pf[j] = v;
            }
        }

        // ---- compute from current buffer ----
        const int b = ci & 1;
#pragma unroll
        for (int kh = 0; kh < 3; kh++) {
            const float* rowp = &sx[b][ty + kh][tx * 4];   // 16B-aligned
            float4 a4 = *(const float4*)(rowp);
            float2 c2 = *(const float2*)(rowp + 4);
            unsigned long long xp[5];
            xp[0] = pack2(a4.x, a4.y);
            xp[1] = pack2(a4.y, a4.z);
            xp[2] = pack2(a4.z, a4.w);
            xp[3] = pack2(a4.w, c2.x);
            xp[4] = pack2(c2.x, c2.y);
#pragma unroll
            for (int kw = 0; kw < 3; kw++) {
                const unsigned long long* wk = &swd[((ci * 9) + kh * 3 + kw) * CO_T];
#pragma unroll
                for (int cp = 0; cp < CO_T; cp += 2) {
                    ulonglong2 w2 = *(const ulonglong2*)(wk + cp);  // LDS.128 bcast
                    fma2(acc[cp][0],     xp[kw],     w2.x);
                    fma2(acc[cp][1],     xp[kw + 2], w2.x);
                    fma2(acc[cp + 1][0], xp[kw],     w2.y);
                    fma2(acc[cp + 1][1], xp[kw + 2], w2.y);
                }
            }
        }

        // ---- store prefetched tile into the other buffer ----
        if (ci + 1 < CIN) {
            const int nb = (ci + 1) & 1;
#pragma unroll
            for (int j = 0; j < 5; j++) {
                int i = tid + 256 * j;
                if (i < (HT + 2) * (WT + 2)) {
                    int r = i / (WT + 2), c = i - r * (WT + 2);
                    sx[nb][r][c] = pf[j];
                }
            }
        }
        __syncthreads();
    }

#pragma unroll
    for (int c = 0; c < CO_T; c++) {
        float bv = bias[co0 + c];
        float p0, p1, p2, p3;
        unpack2(acc[c][0], p0, p1);
        unpack2(acc[c][1], p2, p3);
        float* orow = &d_y[((co0 + c) * HH + (h0 + ty)) * WW + w0 + tx * 4];
        *(float4*)orow = make_float4(p0 + bv, p1 + bv, p2 + bv, p3 + bv);
    }
}

// ===========================================================================
// Register-resident 512-pt FFT: per-lane FFT-16 (regs) x cross-lane FFT-32
// (shfl). Decomposition n = n1 + 32*n2 (lane n1, reg n2);
// forward output X[k2 + 16*k1] at (lane k1, reg k2). Inverse is the mirror.
// ===========================================================================
template<int INV>
__device__ __forceinline__ void fft16_reg(float2 v[16])
{
    float2 t;
    t = v[1];  v[1]  = v[8];  v[8]  = t;
    t = v[2];  v[2]  = v[4];  v[4]  = t;
    t = v[3];  v[3]  = v[12]; v[12] = t;
    t = v[5];  v[5]  = v[10]; v[10] = t;
    t = v[7];  v[7]  = v[14]; v[14] = t;
    t = v[11]; v[11] = v[13]; v[13] = t;

    const float CC[8] = { 1.f,  0.92387953251128674f,  0.70710678118654752f,
                          0.38268343236508977f, 0.f, -0.38268343236508977f,
                         -0.70710678118654752f, -0.92387953251128674f };
    const float SS[8] = { 0.f,  0.38268343236508977f,  0.70710678118654752f,
                          0.92387953251128674f, 1.f,  0.92387953251128674f,
                          0.70710678118654752f,  0.38268343236508977f };
#pragma unroll
    for (int st = 1; st <= 4; st++) {
        const int half = 1 << (st - 1);
#pragma unroll
        for (int j = 0; j < 8; j++) {
            const int pos = j & (half - 1);
            const int i0  = ((j >> (st - 1)) << st) | pos;
            const int i1  = i0 + half;
            const int tj  = pos << (4 - st);
            const float wr = CC[tj];
            const float wi = INV ? SS[tj] : -SS[tj];
            float br = v[i1].x * wr - v[i1].y * wi;
            float bi = v[i1].x * wi + v[i1].y * wr;
            v[i1].x = v[i0].x - br; v[i1].y = v[i0].y - bi;
            v[i0].x += br;          v[i0].y += bi;
        }
    }
}

template<int INV>
__device__ __forceinline__ void fft32_xlane(float2 v[16], int lane)
{
    const unsigned m = 0xffffffffu;
    int rl = __brev(lane) >> 27;
#pragma unroll
    for (int r = 0; r < 16; r++) {
        v[r].x = __shfl_sync(m, v[r].x, rl);
        v[r].y = __shfl_sync(m, v[r].y, rl);
    }
#pragma unroll
    for (int st = 1; st <= 5; st++) {
        const int half = 1 << (st - 1);
        float ang = (INV ? 3.14159265358979323f : -3.14159265358979323f)
                    * (float)(lane & (half - 1)) / (float)half;
        float wi, wr;
        __sincosf(ang, &wi, &wr);
        const float sgn = (lane & half) ? -1.f : 1.f;
        const bool hi = (lane & half) != 0;
#pragma unroll
        for (int r = 0; r < 16; r++) {
            float px = __shfl_xor_sync(m, v[r].x, half);
            float py = __shfl_xor_sync(m, v[r].y, half);
            float bx = hi ? v[r].x : px;
            float by = hi ? v[r].y : py;
            float ax = hi ? px : v[r].x;
            float ay = hi ? py : v[r].y;
            float tx = bx * wr - by * wi;
            float ty = bx * wi + by * wr;
            v[r].x = fmaf(sgn, tx, ax);
            v[r].y = fmaf(sgn, ty, ay);
        }
    }
}

template<int INV>
__device__ __forceinline__ void twiddle512(float2 v[16], int lane)
{
    float ang = (INV ? 6.28318530717958648f : -6.28318530717958648f)
                * (float)lane / 512.f;
    float s, c;
    __sincosf(ang, &s, &c);
    float wr = 1.f, wi = 0.f;
#pragma unroll
    for (int r = 1; r < 16; r++) {
        float nwr = wr * c - wi * s;
        float nwi = wr * s + wi * c;
        wr = nwr; wi = nwi;
        float xr = v[r].x, xi = v[r].y;
        v[r].x = xr * wr - xi * wi;
        v[r].y = xr * wi + xi * wr;
    }
}

__device__ __forceinline__ void fft512_fwd(float2 v[16], int lane)
{
    fft16_reg<0>(v);
    twiddle512<0>(v, lane);
    fft32_xlane<0>(v, lane);
}
__device__ __forceinline__ void fft512_inv(float2 v[16], int lane)
{
    fft32_xlane<1>(v, lane);
    twiddle512<1>(v, lane);
    fft16_reg<1>(v);
}

// XOR swizzle for the k-major float2 slab (logical idx = 8*k + c, k<512, c<8)
__device__ __forceinline__ int swz(int idx) { return idx ^ ((idx >> 7) & 15); }

// ===========================================================================
// Pass 1: forward FFT along H. 8 columns/block, warp-per-column.
// ===========================================================================
__global__ __launch_bounds__(256) void fft_cols_fwd()
{
    __shared__ char raw[32768];
    float*  sIn  = (float*)raw;     // [h*9 + c]
    float2* sOut = (float2*)raw;    // swizzled [8k+c]

    const int tid  = threadIdx.x;
    const int lane = tid & 31;
    const int wp   = tid >> 5;
    const int ch   = blockIdx.y;
    const int w0   = blockIdx.x * 8;

    for (int i = tid; i < 4096; i += 256) {
        int h = i >> 3, c = i & 7;
        sIn[h * 9 + c] = d_y[(ch * HH + h) * WW + w0 + c];
    }
    __syncthreads();

    float2 v[16];
#pragma unroll
    for (int r = 0; r < 16; r++)
        v[r] = make_float2(sIn[(lane + 32 * r) * 9 + wp], 0.f);
    __syncthreads();

    fft512_fwd(v, lane);

#pragma unroll
    for (int r = 0; r < 16; r++) {
        int k = r + 16 * lane;
        sOut[swz((k << 3) | wp)] = v[r];
    }
    __syncthreads();

    for (int i = tid; i < 4096; i += 256) {
        int k = i >> 3, c = i & 7;
        d_spec[(ch * HH + k) * WW + w0 + c] = sOut[swz(i)];
    }
}

// ===========================================================================
// Pass 2: fused forward FFT along W, mask*(1/N^2), inverse FFT along W.
// ===========================================================================
__global__ __launch_bounds__(256) void fft_rows_mask(const float* __restrict__ mask)
{
    __shared__ float sm[8][528];

    const int tid  = threadIdx.x;
    const int lane = tid & 31;
    const int wp   = tid >> 5;
    const int ch   = blockIdx.y;
    const int h    = blockIdx.x * 8 + wp;

    float2* row  = &d_spec[(ch * HH + h) * WW];
    const float* mrow = &mask[(ch * HH + h) * WW];

    float2 v[16];
#pragma unroll
    for (int r = 0; r < 16; r++)
        v[r] = row[lane + 32 * r];
#pragma unroll
    for (int t = 0; t < 16; t++) {
        int i = lane + 32 * t;
        sm[wp][i + (i >> 5)] = mrow[i];
    }

    fft512_fwd(v, lane);
    __syncwarp();

    const float sc = 1.0f / (512.0f * 512.0f);
#pragma unroll
    for (int r = 0; r < 16; r++) {
        int k = r + 16 * lane;
        float mv = sm[wp][k + (k >> 5)] * sc;
        v[r].x *= mv; v[r].y *= mv;
    }

    fft512_inv(v, lane);

#pragma unroll
    for (int r = 0; r < 16; r++)
        row[lane + 32 * r] = v[r];
}

// ===========================================================================
// Pass 3: inverse FFT along H, write real part.
// ===========================================================================
__global__ __launch_bounds__(256) void fft_cols_inv(float* __restrict__ out)
{
    __shared__ char raw[32768];
    float2* sIn  = (float2*)raw;
    float*  sOut = (float*)raw;

    const int tid  = threadIdx.x;
    const int lane = tid & 31;
    const int wp   = tid >> 5;
    const int ch   = blockIdx.y;
    const int w0   = blockIdx.x * 8;

    for (int i = tid; i < 4096; i += 256) {
        int k = i >> 3, c = i & 7;
        sIn[swz(i)] = d_spec[(ch * HH + k) * WW + w0 + c];
    }
    __syncthreads();

    float2 v[16];
#pragma unroll
    for (int r = 0; r < 16; r++) {
        int k = r + 16 * lane;
        v[r] = sIn[swz((k << 3) | wp)];
    }
    __syncthreads();

    fft512_inv(v, lane);

#pragma unroll
    for (int r = 0; r < 16; r++)
        sOut[(lane + 32 * r) * 9 + wp] = v[r].x;
    __syncthreads();

    for (int i = tid; i < 4096; i += 256) {
        int hh = i >> 3, c = i & 7;
        out[(ch * HH + hh) * WW + w0 + c] = sOut[hh * 9 + c];
    }
}

// ===========================================================================
extern "C" void kernel_launch(void* const* d_in, const int* in_sizes, int n_in,
                              void* d_out, int out_size)
{
    const float* x    = (const float*)d_in[0];   // (64,512,512)
    const float* wgt  = (const float*)d_in[1];   // (128,64,3,3)
    const float* bias = (const float*)d_in[2];   // (128,)
    const float* mask = (const float*)d_in[3];   // (128,512,512)
    float* out = (float*)d_out;                  // (128,512,512)

    conv3x3_kernel<<<dim3(WW / WT, HH / HT, COUT / CO_T), 256>>>(x, wgt, bias);
    fft_cols_fwd <<<dim3(WW / 8, COUT), 256>>>();
    fft_rows_mask<<<dim3(HH / 8, COUT), 256>>>(mask);
    fft_cols_inv <<<dim3(WW / 8, COUT), 256>>>(out);
}

// round 10
// speedup vs baseline: 1.9197x; 1.1092x over previous
#include <cuda_runtime.h>
#include <math.h>

#define CIN  64
#define COUT 128
#define HH   512
#define WW   512

__device__ float  d_y[COUT * HH * WW];     // conv output            (128 MB)
__device__ float2 d_spec[(COUT / 2) * HH * WW];  // packed pair spectrum (128 MB)

// ===========================================================================
// Packed fp32x2 helpers (sm_103a dual-FMA path)
// ===========================================================================
__device__ __forceinline__ unsigned long long pack2(float a, float b) {
    unsigned long long r;
    asm("mov.b64 %0, {%1, %2};" : "=l"(r) : "f"(a), "f"(b));
    return r;
}
__device__ __forceinline__ void unpack2(unsigned long long v, float& a, float& b) {
    asm("mov.b64 {%0, %1}, %2;" : "=f"(a), "=f"(b) : "l"(v));
}
__device__ __forceinline__ void fma2(unsigned long long& acc,
                                     unsigned long long x, unsigned long long w) {
    asm("fma.rn.f32x2 %0, %1, %2, %0;" : "+l"(acc) : "l"(x), "l"(w));
}

// ===========================================================================
// Conv 3x3 (round-8 version, unchanged): 8 co x 16 h x 64 w per block.
// ===========================================================================
#define CO_T 8
#define HT   16
#define WT   64
#define XP   68

__global__ __launch_bounds__(256, 2) void conv3x3_kernel(
    const float* __restrict__ x, const float* __restrict__ wgt,
    const float* __restrict__ bias)
{
    __shared__ unsigned long long swd[CIN * 9 * CO_T];   // [ci][k][co], 36.9 KB
    __shared__ float sx[2][HT + 2][XP];

    const int tid = threadIdx.x;
    const int tx  = tid & 15;
    const int ty  = tid >> 4;
    const int w0  = blockIdx.x * WT;
    const int h0  = blockIdx.y * HT;
    const int co0 = blockIdx.z * CO_T;

    for (int i = tid; i < CIN * 9 * CO_T; i += 256) {
        int c   = i & 7;
        int kci = i >> 3;
        int ci  = kci / 9;
        int k   = kci - ci * 9;
        float w = wgt[((co0 + c) * CIN + ci) * 9 + k];
        swd[i] = pack2(w, w);
    }

    for (int i = tid; i < (HT + 2) * (WT + 2); i += 256) {
        int r = i / (WT + 2), c = i - r * (WT + 2);
        int hh = h0 + r - 1, ww = w0 + c - 1;
        float v = 0.f;
        if (hh >= 0 && hh < HH && ww >= 0 && ww < WW)
            v = x[hh * WW + ww];
        sx[0][r][c] = v;
    }
    __syncthreads();

    unsigned long long acc[CO_T][2];
#pragma unroll
    for (int c = 0; c < CO_T; c++) { acc[c][0] = 0ull; acc[c][1] = 0ull; }

    for (int ci = 0; ci < CIN; ci++) {
        float pf[5];
        if (ci + 1 < CIN) {
            const float* xn = x + (ci + 1) * HH * WW;
#pragma unroll
            for (int j = 0; j < 5; j++) {
                int i = tid + 256 * j;
                float v = 0.f;
                if (i < (HT + 2) * (WT + 2)) {
                    int r = i / (WT + 2), c = i - r * (WT + 2);
                    int hh = h0 + r - 1, ww = w0 + c - 1;
                    if (hh >= 0 && hh < HH && ww >= 0 && ww < WW)
                        v = xn[hh * WW + ww];
                }
                pf[j] = v;
            }
        }

        const int b = ci & 1;
#pragma unroll
        for (int kh = 0; kh < 3; kh++) {
            const float* rowp = &sx[b][ty + kh][tx * 4];
            float4 a4 = *(const float4*)(rowp);
            float2 c2 = *(const float2*)(rowp + 4);
            unsigned long long xp[5];
            xp[0] = pack2(a4.x, a4.y);
            xp[1] = pack2(a4.y, a4.z);
            xp[2] = pack2(a4.z, a4.w);
            xp[3] = pack2(a4.w, c2.x);
            xp[4] = pack2(c2.x, c2.y);
#pragma unroll
            for (int kw = 0; kw < 3; kw++) {
                const unsigned long long* wk = &swd[((ci * 9) + kh * 3 + kw) * CO_T];
#pragma unroll
                for (int cp = 0; cp < CO_T; cp += 2) {
                    ulonglong2 w2 = *(const ulonglong2*)(wk + cp);
                    fma2(acc[cp][0],     xp[kw],     w2.x);
                    fma2(acc[cp][1],     xp[kw + 2], w2.x);
                    fma2(acc[cp + 1][0], xp[kw],     w2.y);
                    fma2(acc[cp + 1][1], xp[kw + 2], w2.y);
                }
            }
        }

        if (ci + 1 < CIN) {
            const int nb = (ci + 1) & 1;
#pragma unroll
            for (int j = 0; j < 5; j++) {
                int i = tid + 256 * j;
                if (i < (HT + 2) * (WT + 2)) {
                    int r = i / (WT + 2), c = i - r * (WT + 2);
                    sx[nb][r][c] = pf[j];
                }
            }
        }
        __syncthreads();
    }

#pragma unroll
    for (int c = 0; c < CO_T; c++) {
        float bv = bias[co0 + c];
        float p0, p1, p2, p3;
        unpack2(acc[c][0], p0, p1);
        unpack2(acc[c][1], p2, p3);
        float* orow = &d_y[((co0 + c) * HH + (h0 + ty)) * WW + w0 + tx * 4];
        *(float4*)orow = make_float4(p0 + bv, p1 + bv, p2 + bv, p3 + bv);
    }
}

// ===========================================================================
// Register-resident 512-pt FFT (unchanged core)
// fwd: in (lane n1, reg n2) n=n1+32*n2 -> out (lane k1, reg k2) k=r+16*lane
// inv: mirror.
// ===========================================================================
template<int INV>
__device__ __forceinline__ void fft16_reg(float2 v[16])
{
    float2 t;
    t = v[1];  v[1]  = v[8];  v[8]  = t;
    t = v[2];  v[2]  = v[4];  v[4]  = t;
    t = v[3];  v[3]  = v[12]; v[12] = t;
    t = v[5];  v[5]  = v[10]; v[10] = t;
    t = v[7];  v[7]  = v[14]; v[14] = t;
    t = v[11]; v[11] = v[13]; v[13] = t;

    const float CC[8] = { 1.f,  0.92387953251128674f,  0.70710678118654752f,
                          0.38268343236508977f, 0.f, -0.38268343236508977f,
                         -0.70710678118654752f, -0.92387953251128674f };
    const float SS[8] = { 0.f,  0.38268343236508977f,  0.70710678118654752f,
                          0.92387953251128674f, 1.f,  0.92387953251128674f,
                          0.70710678118654752f,  0.38268343236508977f };
#pragma unroll
    for (int st = 1; st <= 4; st++) {
        const int half = 1 << (st - 1);
#pragma unroll
        for (int j = 0; j < 8; j++) {
            const int pos = j & (half - 1);
            const int i0  = ((j >> (st - 1)) << st) | pos;
            const int i1  = i0 + half;
            const int tj  = pos << (4 - st);
            const float wr = CC[tj];
            const float wi = INV ? SS[tj] : -SS[tj];
            float br = v[i1].x * wr - v[i1].y * wi;
            float bi = v[i1].x * wi + v[i1].y * wr;
            v[i1].x = v[i0].x - br; v[i1].y = v[i0].y - bi;
            v[i0].x += br;          v[i0].y += bi;
        }
    }
}

template<int INV>
__device__ __forceinline__ void fft32_xlane(float2 v[16], int lane)
{
    const unsigned m = 0xffffffffu;
    int rl = __brev(lane) >> 27;
#pragma unroll
    for (int r = 0; r < 16; r++) {
        v[r].x = __shfl_sync(m, v[r].x, rl);
        v[r].y = __shfl_sync(m, v[r].y, rl);
    }
#pragma unroll
    for (int st = 1; st <= 5; st++) {
        const int half = 1 << (st - 1);
        float ang = (INV ? 3.14159265358979323f : -3.14159265358979323f)
                    * (float)(lane & (half - 1)) / (float)half;
        float wi, wr;
        __sincosf(ang, &wi, &wr);
        const float sgn = (lane & half) ? -1.f : 1.f;
        const bool hi = (lane & half) != 0;
#pragma unroll
        for (int r = 0; r < 16; r++) {
            float px = __shfl_xor_sync(m, v[r].x, half);
            float py = __shfl_xor_sync(m, v[r].y, half);
            float bx = hi ? v[r].x : px;
            float by = hi ? v[r].y : py;
            float ax = hi ? px : v[r].x;
            float ay = hi ? py : v[r].y;
            float tx = bx * wr - by * wi;
            float ty = bx * wi + by * wr;
            v[r].x = fmaf(sgn, tx, ax);
            v[r].y = fmaf(sgn, ty, ay);
        }
    }
}

template<int INV>
__device__ __forceinline__ void twiddle512(float2 v[16], int lane)
{
    float ang = (INV ? 6.28318530717958648f : -6.28318530717958648f)
                * (float)lane / 512.f;
    float s, c;
    __sincosf(ang, &s, &c);
    float wr = 1.f, wi = 0.f;
#pragma unroll
    for (int r = 1; r < 16; r++) {
        float nwr = wr * c - wi * s;
        float nwi = wr * s + wi * c;
        wr = nwr; wi = nwi;
        float xr = v[r].x, xi = v[r].y;
        v[r].x = xr * wr - xi * wi;
        v[r].y = xr * wi + xi * wr;
    }
}

__device__ __forceinline__ void fft512_fwd(float2 v[16], int lane)
{
    fft16_reg<0>(v);
    twiddle512<0>(v, lane);
    fft32_xlane<0>(v, lane);
}
__device__ __forceinline__ void fft512_inv(float2 v[16], int lane)
{
    fft32_xlane<1>(v, lane);
    twiddle512<1>(v, lane);
    fft16_reg<1>(v);
}

// XOR swizzle for the k-major float2 slab (logical idx = 8*k + c)
__device__ __forceinline__ int swz(int idx) { return idx ^ ((idx >> 7) & 15); }
// padded index helpers
__device__ __forceinline__ int padz(int i) { return i + (i >> 4); }   // float2 z rows
__device__ __forceinline__ int padm(int i) { return i + (i >> 5); }   // float mask rows

// ===========================================================================
// Pass 1: column FFT of packed pair z = y[2p] + i*y[2p+1].
// 8 columns/block, warp-per-column. Output d_spec[p][k][w].
// ===========================================================================
__global__ __launch_bounds__(256) void fft_cols_fwd2()
{
    __shared__ char raw[36864];
    float2* sIn  = (float2*)raw;   // [h*9 + c], 4608 float2
    float2* sOut = (float2*)raw;   // swizzled [8k+c], 4096 float2

    const int tid  = threadIdx.x;
    const int lane = tid & 31;
    const int wp   = tid >> 5;
    const int p    = blockIdx.y;           // channel pair
    const int w0   = blockIdx.x * 8;

    const float* y1 = &d_y[(2 * p)     * HH * WW];
    const float* y2 = &d_y[(2 * p + 1) * HH * WW];
    for (int i = tid; i < 4096; i += 256) {
        int h = i >> 3, c = i & 7;
        int g = h * WW + w0 + c;
        sIn[h * 9 + c] = make_float2(y1[g], y2[g]);
    }
    __syncthreads();

    float2 v[16];
#pragma unroll
    for (int r = 0; r < 16; r++)
        v[r] = sIn[(lane + 32 * r) * 9 + wp];
    __syncthreads();   // all reads of sIn done before sOut overwrites

    fft512_fwd(v, lane);

#pragma unroll
    for (int r = 0; r < 16; r++) {
        int k = r + 16 * lane;
        sOut[swz((k << 3) | wp)] = v[r];
    }
    __syncthreads();

    for (int i = tid; i < 4096; i += 256) {
        int k = i >> 3, c = i & 7;
        d_spec[(p * HH + k) * WW + w0 + c] = sOut[swz(i)];
    }
}

// ===========================================================================
// Pass 2: per row-pair (k1, 512-k1): forward row FFT, Hermitian split into
// the two channels' spectra, symmetrized-mask multiply (with 1/N^2),
// recombine, inverse row FFT. 2 row-pairs per 128-thread block.
//   warp role 0 -> row k1 (A), role 1 -> row (512-k1)&511 (B).
// Math (per k2, r2 = (512-k2)&511, c4 = 0.25/N^2):
//   role0: s = zA[k]+conj(zB[r2]); d = zA[k]-conj(zB[r2])   (s=(sx,sy), d=(dx,dy))
//          m1 = (M1A[k]+M1B[r2])c4; m2 = (M2A[k]+M2B[r2])c4
//          Y = (m1*sx + m2*dx, m1*sy + m2*dy)
//   role1: s' = zA[r2]+conj(zB[k]); d' = zA[r2]-conj(zB[k])
//          m1r = (M1A[r2]+M1B[k])c4; m2r = (M2A[r2]+M2B[k])c4
//          Y = (m1r*s'x - m2r*d'x, -m1r*s'y + m2r*d'y)
// ===========================================================================
__global__ __launch_bounds__(128) void fft_rows_mask2(const float* __restrict__ mask)
{
    __shared__ float2 zbuf[2][2][544];   // [pairSlot][A/B][padded 512]
    __shared__ float  mbuf[2][4][528];   // [pairSlot][m1A,m1B,m2A,m2B][padded 512]

    const int tid   = threadIdx.x;
    const int lane  = tid & 31;
    const int wp    = tid >> 5;          // 0..3
    const int slot  = wp >> 1;
    const int role  = wp & 1;
    const int p     = blockIdx.y;
    const int k1    = blockIdx.x * 2 + slot;
    const bool act  = (k1 <= 256);

    const int rowA  = k1;
    const int rowB  = (512 - k1) & 511;
    const int myrow = role ? rowB : rowA;

    float2 v[16];
    if (act) {
        const float2* srow = &d_spec[(p * HH + myrow) * WW];
#pragma unroll
        for (int r = 0; r < 16; r++)
            v[r] = srow[lane + 32 * r];

        const float* m1 = &mask[((2 * p)     * HH + myrow) * WW];
        const float* m2 = &mask[((2 * p + 1) * HH + myrow) * WW];
        float* d1 = mbuf[slot][role];        // m1A or m1B
        float* d2 = mbuf[slot][2 + role];    // m2A or m2B
#pragma unroll
        for (int t = 0; t < 16; t++) {
            int i = lane + 32 * t;
            d1[padm(i)] = m1[i];
            d2[padm(i)] = m2[i];
        }

        fft512_fwd(v, lane);

        float2* zme = zbuf[slot][role];
#pragma unroll
        for (int r = 0; r < 16; r++) {
            int k = r + 16 * lane;
            zme[padz(k)] = v[r];
        }
    }
    __syncthreads();

    if (act) {
        const float c4 = 0.25f / (512.0f * 512.0f);
        const float* m1A = mbuf[slot][0];
        const float* m1B = mbuf[slot][1];
        const float* m2A = mbuf[slot][2];
        const float* m2B = mbuf[slot][3];
        const float2* zA = zbuf[slot][0];
        const float2* zB = zbuf[slot][1];

#pragma unroll
        for (int r = 0; r < 16; r++) {
            int k  = r + 16 * lane;
            int r2 = (512 - k) & 511;
            if (role == 0) {
                float2 zb = zB[padz(r2)];
                float sx = v[r].x + zb.x, sy = v[r].y - zb.y;
                float dx = v[r].x - zb.x, dy = v[r].y + zb.y;
                float m1v = (m1A[padm(k)] + m1B[padm(r2)]) * c4;
                float m2v = (m2A[padm(k)] + m2B[padm(r2)]) * c4;
                v[r] = make_float2(m1v * sx + m2v * dx, m1v * sy + m2v * dy);
            } else {
                float2 za = zA[padz(r2)];
                float sx = za.x + v[r].x, sy = za.y - v[r].y;
                float dx = za.x - v[r].x, dy = za.y + v[r].y;
                float m1v = (m1A[padm(r2)] + m1B[padm(k)]) * c4;
                float m2v = (m2A[padm(r2)] + m2B[padm(k)]) * c4;
                v[r] = make_float2(m1v * sx - m2v * dx, -m1v * sy + m2v * dy);
            }
        }

        fft512_inv(v, lane);

        if (!(role == 1 && rowB == rowA)) {
            float2* orow = &d_spec[(p * HH + myrow) * WW];
#pragma unroll
            for (int r = 0; r < 16; r++)
                orow[lane + 32 * r] = v[r];
        }
    }
}

// ===========================================================================
// Pass 3: inverse column FFT; Re -> channel 2p, Im -> channel 2p+1.
// ===========================================================================
__global__ __launch_bounds__(256) void fft_cols_inv2(float* __restrict__ out)
{
    __shared__ char raw[36864];
    float2* sIn  = (float2*)raw;   // swizzled [8k+c]
    float2* sOut = (float2*)raw;   // [h*9 + c]

    const int tid  = threadIdx.x;
    const int lane = tid & 31;
    const int wp   = tid >> 5;
    const int p    = blockIdx.y;
    const int w0   = blockIdx.x * 8;

    for (int i = tid; i < 4096; i += 256) {
        int k = i >> 3, c = i & 7;
        sIn[swz(i)] = d_spec[(p * HH + k) * WW + w0 + c];
    }
    __syncthreads();

    float2 v[16];
#pragma unroll
    for (int r = 0; r < 16; r++) {
        int k = r + 16 * lane;
        v[r] = sIn[swz((k << 3) | wp)];
    }
    __syncthreads();

    fft512_inv(v, lane);

#pragma unroll
    for (int r = 0; r < 16; r++)
        sOut[(lane + 32 * r) * 9 + wp] = v[r];
    __syncthreads();

    float* o1 = &out[(2 * p)     * HH * WW];
    float* o2 = &out[(2 * p + 1) * HH * WW];
    for (int i = tid; i < 4096; i += 256) {
        int hh = i >> 3, c = i & 7;
        float2 s = sOut[hh * 9 + c];
        int g = hh * WW + w0 + c;
        o1[g] = s.x;
        o2[g] = s.y;
    }
}

// ===========================================================================
extern "C" void kernel_launch(void* const* d_in, const int* in_sizes, int n_in,
                              void* d_out, int out_size)
{
    const float* x    = (const float*)d_in[0];   // (64,512,512)
    const float* wgt  = (const float*)d_in[1];   // (128,64,3,3)
    const float* bias = (const float*)d_in[2];   // (128,)
    const float* mask = (const float*)d_in[3];   // (128,512,512)
    float* out = (float*)d_out;                  // (128,512,512)

    conv3x3_kernel<<<dim3(WW / WT, HH / HT, COUT / CO_T), 256>>>(x, wgt, bias);
    fft_cols_fwd2 <<<dim3(WW / 8, COUT / 2), 256>>>();
    fft_rows_mask2<<<dim3(129, COUT / 2), 128>>>(mask);
    fft_cols_inv2 <<<dim3(WW / 8, COUT / 2), 256>>>(out);
}

// round 12
// speedup vs baseline: 1.9750x; 1.0288x over previous
#include <cuda_runtime.h>
#include <math.h>

#define CIN  64
#define COUT 128
#define HH   512
#define WW   512

__device__ float  d_y[COUT * HH * WW];           // conv output          (128 MB)
__device__ float2 d_spec[(COUT / 2) * HH * WW];  // packed pair spectrum (128 MB)

// ===========================================================================
// Packed fp32x2 helpers (sm_103a dual-FMA path)
// ===========================================================================
__device__ __forceinline__ unsigned long long pack2(float a, float b) {
    unsigned long long r;
    asm("mov.b64 %0, {%1, %2};" : "=l"(r) : "f"(a), "f"(b));
    return r;
}
__device__ __forceinline__ void unpack2(unsigned long long v, float& a, float& b) {
    asm("mov.b64 {%0, %1}, %2;" : "=f"(a), "=f"(b) : "l"(v));
}
__device__ __forceinline__ void fma2(unsigned long long& acc,
                                     unsigned long long x, unsigned long long w) {
    asm("fma.rn.f32x2 %0, %1, %2, %0;" : "+l"(acc) : "l"(x), "l"(w));
}

// ===========================================================================
// Conv 3x3 (cross-correlation, same padding), packed fp32x2 FMA.
// Block: 8 co x 16 h x 64 w. Thread: 8 co x 4 w px.
// NEW: all prefetch/store addressing precomputed ONCE per thread (gOff/sOff);
// the per-ci loop does only predicated LDG/STS off bumped pointers.
// ===========================================================================
#define CO_T 8
#define HT   16
#define WT   64
#define XP   68
#define XELEM ((HT + 2) * (WT + 2))   /* 1188 */

__global__ __launch_bounds__(256, 2) void conv3x3_kernel(
    const float* __restrict__ x, const float* __restrict__ wgt,
    const float* __restrict__ bias)
{
    __shared__ unsigned long long swd[CIN * 9 * CO_T];   // [ci][k][co], 36.9 KB
    __shared__ float sx[2][HT + 2][XP];                  // 9.8 KB

    const int tid = threadIdx.x;
    const int tx  = tid & 15;
    const int ty  = tid >> 4;
    const int w0  = blockIdx.x * WT;
    const int h0  = blockIdx.y * HT;
    const int co0 = blockIdx.z * CO_T;

    // ---- one-time weight preload: swd[(ci*9 + k)*8 + c] = dup(w[co0+c][ci][k])
    for (int i = tid; i < CIN * 9 * CO_T; i += 256) {
        int c   = i & 7;
        int kci = i >> 3;
        int ci  = kci / 9;
        int k   = kci - ci * 9;
        float w = wgt[((co0 + c) * CIN + ci) * 9 + k];
        swd[i] = pack2(w, w);
    }

    // ---- one-time addressing precompute (loop-invariant across ci) ----
    int      gOff[5];   // global offset within one channel plane, -1 => halo zero
    unsigned sOff[5];   // smem float offset within one buffer, ~0u => inactive
#pragma unroll
    for (int j = 0; j < 5; j++) {
        int i = tid + 256 * j;
        gOff[j] = -1; sOff[j] = 0xFFFFFFFFu;
        if (i < XELEM) {
            int r = i / (WT + 2), c = i - r * (WT + 2);
            sOff[j] = r * XP + c;
            int hh = h0 + r - 1, ww = w0 + c - 1;
            if (hh >= 0 && hh < HH && ww >= 0 && ww < WW)
                gOff[j] = hh * WW + ww;
        }
    }
    float* const sx0 = &sx[0][0][0];
    float* const sx1 = &sx[1][0][0];
    const float* const xb0 = &sx[0][ty][tx * 4];
    const float* const xb1 = &sx[1][ty][tx * 4];

    // ---- initial x tile (ci = 0) ----
#pragma unroll
    for (int j = 0; j < 5; j++)
        if (sOff[j] != 0xFFFFFFFFu)
            sx0[sOff[j]] = (gOff[j] >= 0) ? x[gOff[j]] : 0.f;
    __syncthreads();

    unsigned long long acc[CO_T][2];
#pragma unroll
    for (int c = 0; c < CO_T; c++) { acc[c][0] = 0ull; acc[c][1] = 0ull; }

    const float* xn = x + HH * WW;                 // next channel plane
    const unsigned long long* wci = swd;           // walks by 72 per ci

    for (int ci = 0; ci < CIN; ci++) {
        // ---- prefetch next channel tile (precomputed offsets) ----
        float pf[5];
        const bool more = (ci + 1 < CIN);
        if (more) {
#pragma unroll
            for (int j = 0; j < 5; j++)
                pf[j] = (gOff[j] >= 0) ? xn[gOff[j]] : 0.f;
        }

        // ---- compute from current buffer ----
        const float* rbase = (ci & 1) ? xb1 : xb0;
#pragma unroll
        for (int kh = 0; kh < 3; kh++) {
            const float* rowp = rbase + kh * XP;
            float4 a4 = *(const float4*)(rowp);
            float2 c2 = *(const float2*)(rowp + 4);
            unsigned long long xp[5];
            xp[0] = pack2(a4.x, a4.y);
            xp[1] = pack2(a4.y, a4.z);
            xp[2] = pack2(a4.z, a4.w);
            xp[3] = pack2(a4.w, c2.x);
            xp[4] = pack2(c2.x, c2.y);
#pragma unroll
            for (int kw = 0; kw < 3; kw++) {
                const unsigned long long* wk = wci + (kh * 3 + kw) * CO_T;
#pragma unroll
                for (int cp = 0; cp < CO_T; cp += 2) {
                    ulonglong2 w2 = *(const ulonglong2*)(wk + cp);   // LDS.128 bcast
                    fma2(acc[cp][0],     xp[kw],     w2.x);
                    fma2(acc[cp][1],     xp[kw + 2], w2.x);
                    fma2(acc[cp + 1][0], xp[kw],     w2.y);
                    fma2(acc[cp + 1][1], xp[kw + 2], w2.y);
                }
            }
        }

        // ---- store prefetched tile into the other buffer ----
        if (more) {
            float* dst = (ci & 1) ? sx0 : sx1;
#pragma unroll
            for (int j = 0; j < 5; j++)
                if (sOff[j] != 0xFFFFFFFFu) dst[sOff[j]] = pf[j];
        }
        __syncthreads();
        xn  += HH * WW;
        wci += 9 * CO_T;
    }

#pragma unroll
    for (int c = 0; c < CO_T; c++) {
        float bv = bias[co0 + c];
        float p0, p1, p2, p3;
        unpack2(acc[c][0], p0, p1);
        unpack2(acc[c][1], p2, p3);
        float* orow = &d_y[((co0 + c) * HH + (h0 + ty)) * WW + w0 + tx * 4];
        *(float4*)orow = make_float4(p0 + bv, p1 + bv, p2 + bv, p3 + bv);
    }
}

// ===========================================================================
// Register-resident 512-pt FFT (unchanged core)
// ===========================================================================
template<int INV>
__device__ __forceinline__ void fft16_reg(float2 v[16])
{
    float2 t;
    t = v[1];  v[1]  = v[8];  v[8]  = t;
    t = v[2];  v[2]  = v[4];  v[4]  = t;
    t = v[3];  v[3]  = v[12]; v[12] = t;
    t = v[5];  v[5]  = v[10]; v[10] = t;
    t = v[7];  v[7]  = v[14]; v[14] = t;
    t = v[11]; v[11] = v[13]; v[13] = t;

    const float CC[8] = { 1.f,  0.92387953251128674f,  0.70710678118654752f,
                          0.38268343236508977f, 0.f, -0.38268343236508977f,
                         -0.70710678118654752f, -0.92387953251128674f };
    const float SS[8] = { 0.f,  0.38268343236508977f,  0.70710678118654752f,
                          0.92387953251128674f, 1.f,  0.92387953251128674f,
                          0.70710678118654752f,  0.38268343236508977f };
#pragma unroll
    for (int st = 1; st <= 4; st++) {
        const int half = 1 << (st - 1);
#pragma unroll
        for (int j = 0; j < 8; j++) {
            const int pos = j & (half - 1);
            const int i0  = ((j >> (st - 1)) << st) | pos;
            const int i1  = i0 + half;
            const int tj  = pos << (4 - st);
            const float wr = CC[tj];
            const float wi = INV ? SS[tj] : -SS[tj];
            float br = v[i1].x * wr - v[i1].y * wi;
            float bi = v[i1].x * wi + v[i1].y * wr;
            v[i1].x = v[i0].x - br; v[i1].y = v[i0].y - bi;
            v[i0].x += br;          v[i0].y += bi;
        }
    }
}

template<int INV>
__device__ __forceinline__ void fft32_xlane(float2 v[16], int lane)
{
    const unsigned m = 0xffffffffu;
    int rl = __brev(lane) >> 27;
#pragma unroll
    for (int r = 0; r < 16; r++) {
        v[r].x = __shfl_sync(m, v[r].x, rl);
        v[r].y = __shfl_sync(m, v[r].y, rl);
    }
#pragma unroll
    for (int st = 1; st <= 5; st++) {
        const int half = 1 << (st - 1);
        float ang = (INV ? 3.14159265358979323f : -3.14159265358979323f)
                    * (float)(lane & (half - 1)) / (float)half;
        float wi, wr;
        __sincosf(ang, &wi, &wr);
        const float sgn = (lane & half) ? -1.f : 1.f;
        const bool hi = (lane & half) != 0;
#pragma unroll
        for (int r = 0; r < 16; r++) {
            float px = __shfl_xor_sync(m, v[r].x, half);
            float py = __shfl_xor_sync(m, v[r].y, half);
            float bx = hi ? v[r].x : px;
            float by = hi ? v[r].y : py;
            float ax = hi ? px : v[r].x;
            float ay = hi ? py : v[r].y;
            float tx = bx * wr - by * wi;
            float ty = bx * wi + by * wr;
            v[r].x = fmaf(sgn, tx, ax);
            v[r].y = fmaf(sgn, ty, ay);
        }
    }
}

template<int INV>
__device__ __forceinline__ void twiddle512(float2 v[16], int lane)
{
    float ang = (INV ? 6.28318530717958648f : -6.28318530717958648f)
                * (float)lane / 512.f;
    float s, c;
    __sincosf(ang, &s, &c);
    float wr = 1.f, wi = 0.f;
#pragma unroll
    for (int r = 1; r < 16; r++) {
        float nwr = wr * c - wi * s;
        float nwi = wr * s + wi * c;
        wr = nwr; wi = nwi;
        float xr = v[r].x, xi = v[r].y;
        v[r].x = xr * wr - xi * wi;
        v[r].y = xr * wi + xi * wr;
    }
}

__device__ __forceinline__ void fft512_fwd(float2 v[16], int lane)
{
    fft16_reg<0>(v);
    twiddle512<0>(v, lane);
    fft32_xlane<0>(v, lane);
}
__device__ __forceinline__ void fft512_inv(float2 v[16], int lane)
{
    fft32_xlane<1>(v, lane);
    twiddle512<1>(v, lane);
    fft16_reg<1>(v);
}

__device__ __forceinline__ int swz(int idx) { return idx ^ ((idx >> 7) & 15); }
__device__ __forceinline__ int padz(int i) { return i + (i >> 4); }
__device__ __forceinline__ int padm(int i) { return i + (i >> 5); }

// ===========================================================================
// Pass 1: column FFT of packed pair z = y[2p] + i*y[2p+1].
// ===========================================================================
__global__ __launch_bounds__(256) void fft_cols_fwd2()
{
    __shared__ char raw[36864];
    float2* sIn  = (float2*)raw;
    float2* sOut = (float2*)raw;

    const int tid  = threadIdx.x;
    const int lane = tid & 31;
    const int wp   = tid >> 5;
    const int p    = blockIdx.y;
    const int w0   = blockIdx.x * 8;

    const float* y1 = &d_y[(2 * p)     * HH * WW];
    const float* y2 = &d_y[(2 * p + 1) * HH * WW];
    for (int i = tid; i < 4096; i += 256) {
        int h = i >> 3, c = i & 7;
        int g = h * WW + w0 + c;
        sIn[h * 9 + c] = make_float2(y1[g], y2[g]);
    }
    __syncthreads();

    float2 v[16];
#pragma unroll
    for (int r = 0; r < 16; r++)
        v[r] = sIn[(lane + 32 * r) * 9 + wp];
    __syncthreads();

    fft512_fwd(v, lane);

#pragma unroll
    for (int r = 0; r < 16; r++) {
        int k = r + 16 * lane;
        sOut[swz((k << 3) | wp)] = v[r];
    }
    __syncthreads();

    for (int i = tid; i < 4096; i += 256) {
        int k = i >> 3, c = i & 7;
        d_spec[(p * HH + k) * WW + w0 + c] = sOut[swz(i)];
    }
}

// ===========================================================================
// Pass 2: Hermitian-split row pass (unchanged from round 10).
// ===========================================================================
__global__ __launch_bounds__(128) void fft_rows_mask2(const float* __restrict__ mask)
{
    __shared__ float2 zbuf[2][2][544];
    __shared__ float  mbuf[2][4][528];

    const int tid   = threadIdx.x;
    const int lane  = tid & 31;
    const int wp    = tid >> 5;
    const int slot  = wp >> 1;
    const int role  = wp & 1;
    const int p     = blockIdx.y;
    const int k1    = blockIdx.x * 2 + slot;
    const bool act  = (k1 <= 256);

    const int rowA  = k1;
    const int rowB  = (512 - k1) & 511;
    const int myrow = role ? rowB : rowA;

    float2 v[16];
    if (act) {
        const float2* srow = &d_spec[(p * HH + myrow) * WW];
#pragma unroll
        for (int r = 0; r < 16; r++)
            v[r] = srow[lane + 32 * r];

        const float* m1 = &mask[((2 * p)     * HH + myrow) * WW];
        const float* m2 = &mask[((2 * p + 1) * HH + myrow) * WW];
        float* d1 = mbuf[slot][role];
        float* d2 = mbuf[slot][2 + role];
#pragma unroll
        for (int t = 0; t < 16; t++) {
            int i = lane + 32 * t;
            d1[padm(i)] = m1[i];
            d2[padm(i)] = m2[i];
        }

        fft512_fwd(v, lane);

        float2* zme = zbuf[slot][role];
#pragma unroll
        for (int r = 0; r < 16; r++) {
            int k = r + 16 * lane;
            zme[padz(k)] = v[r];
        }
    }
    __syncthreads();

    if (act) {
        const float c4 = 0.25f / (512.0f * 512.0f);
        const float* m1A = mbuf[slot][0];
        const float* m1B = mbuf[slot][1];
        const float* m2A = mbuf[slot][2];
        const float* m2B = mbuf[slot][3];
        const float2* zA = zbuf[slot][0];
        const float2* zB = zbuf[slot][1];

#pragma unroll
        for (int r = 0; r < 16; r++) {
            int k  = r + 16 * lane;
            int r2 = (512 - k) & 511;
            if (role == 0) {
                float2 zb = zB[padz(r2)];
                float sx = v[r].x + zb.x, sy = v[r].y - zb.y;
                float dx = v[r].x - zb.x, dy = v[r].y + zb.y;
                float m1v = (m1A[padm(k)] + m1B[padm(r2)]) * c4;
                float m2v = (m2A[padm(k)] + m2B[padm(r2)]) * c4;
                v[r] = make_float2(m1v * sx + m2v * dx, m1v * sy + m2v * dy);
            } else {
                float2 za = zA[padz(r2)];
                float sx = za.x + v[r].x, sy = za.y - v[r].y;
                float dx = za.x - v[r].x, dy = za.y + v[r].y;
                float m1v = (m1A[padm(r2)] + m1B[padm(k)]) * c4;
                float m2v = (m2A[padm(r2)] + m2B[padm(k)]) * c4;
                v[r] = make_float2(m1v * sx - m2v * dx, -m1v * sy + m2v * dy);
            }
        }

        fft512_inv(v, lane);

        if (!(role == 1 && rowB == rowA)) {
            float2* orow = &d_spec[(p * HH + myrow) * WW];
#pragma unroll
            for (int r = 0; r < 16; r++)
                orow[lane + 32 * r] = v[r];
        }
    }
}

// ===========================================================================
// Pass 3: inverse column FFT; Re -> channel 2p, Im -> channel 2p+1.
// ===========================================================================
__global__ __launch_bounds__(256) void fft_cols_inv2(float* __restrict__ out)
{
    __shared__ char raw[36864];
    float2* sIn  = (float2*)raw;
    float2* sOut = (float2*)raw;

    const int tid  = threadIdx.x;
    const int lane = tid & 31;
    const int wp   = tid >> 5;
    const int p    = blockIdx.y;
    const int w0   = blockIdx.x * 8;

    for (int i = tid; i < 4096; i += 256) {
        int k = i >> 3, c = i & 7;
        sIn[swz(i)] = d_spec[(p * HH + k) * WW + w0 + c];
    }
    __syncthreads();

    float2 v[16];
#pragma unroll
    for (int r = 0; r < 16; r++) {
        int k = r + 16 * lane;
        v[r] = sIn[swz((k << 3) | wp)];
    }
    __syncthreads();

    fft512_inv(v, lane);

#pragma unroll
    for (int r = 0; r < 16; r++)
        sOut[(lane + 32 * r) * 9 + wp] = v[r];
    __syncthreads();

    float* o1 = &out[(2 * p)     * HH * WW];
    float* o2 = &out[(2 * p + 1) * HH * WW];
    for (int i = tid; i < 4096; i += 256) {
        int hh = i >> 3, c = i & 7;
        float2 s = sOut[hh * 9 + c];
        int g = hh * WW + w0 + c;
        o1[g] = s.x;
        o2[g] = s.y;
    }
}

// ===========================================================================
extern "C" void kernel_launch(void* const* d_in, const int* in_sizes, int n_in,
                              void* d_out, int out_size)
{
    const float* x    = (const float*)d_in[0];   // (64,512,512)
    const float* wgt  = (const float*)d_in[1];   // (128,64,3,3)
    const float* bias = (const float*)d_in[2];   // (128,)
    const float* mask = (const float*)d_in[3];   // (128,512,512)
    float* out = (float*)d_out;                  // (128,512,512)

    conv3x3_kernel<<<dim3(WW / WT, HH / HT, COUT / CO_T), 256>>>(x, wgt, bias);
    fft_cols_fwd2 <<<dim3(WW / 8, COUT / 2), 256>>>();
    fft_rows_mask2<<<dim3(129, COUT / 2), 128>>>(mask);
    fft_cols_inv2 <<<dim3(WW / 8, COUT / 2), 256>>>(out);
}

// round 14
// speedup vs baseline: 2.1134x; 1.0701x over previous
#include <cuda_runtime.h>
#include <math.h>

#define CIN  64
#define COUT 128
#define HH   512
#define WW   512

__device__ float  d_y[COUT * HH * WW];           // conv output          (128 MB)
__device__ float2 d_spec[(COUT / 2) * HH * WW];  // packed pair spectrum (128 MB)

// ===========================================================================
// Packed fp32x2 helpers (sm_103a dual-FMA path)
// ===========================================================================
__device__ __forceinline__ unsigned long long pack2(float a, float b) {
    unsigned long long r;
    asm("mov.b64 %0, {%1, %2};" : "=l"(r) : "f"(a), "f"(b));
    return r;
}
__device__ __forceinline__ void unpack2(unsigned long long v, float& a, float& b) {
    asm("mov.b64 {%0, %1}, %2;" : "=f"(a), "=f"(b) : "l"(v));
}
__device__ __forceinline__ void fma2(unsigned long long& acc,
                                     unsigned long long x, unsigned long long w) {
    asm("fma.rn.f32x2 %0, %1, %2, %0;" : "+l"(acc) : "l"(x), "l"(w));
}

// ===========================================================================
// Conv 3x3 (cross-correlation, same padding), packed fp32x2 FMA.
// Block: 8 co x 16 h x 64 w. Thread: 8 co x 4 w px.
// NO x smem: each thread LDG.128s its 3 input rows (L1 absorbs 3x kh reuse);
// w-halo via in-warp shfl (warp = 2 ty-rows x 16 tx), edge lanes patch with
// predicated scalar LDG. Zero barriers in the ci loop -> 3 CTAs/SM.
// ===========================================================================
#define CO_T 8
#define HT   16
#define WT   64

__global__ __launch_bounds__(256, 3) void conv3x3_kernel(
    const float* __restrict__ x, const float* __restrict__ wgt,
    const float* __restrict__ bias)
{
    __shared__ unsigned long long swd[CIN * 9 * CO_T];   // [ci][k][co], 36.9 KB

    const int tid = threadIdx.x;
    const int tx  = tid & 15;    // 16 groups along W, 4 px each
    const int ty  = tid >> 4;    // 16 rows
    const int w0  = blockIdx.x * WT;
    const int h0  = blockIdx.y * HT;
    const int co0 = blockIdx.z * CO_T;

    // ---- one-time weight preload: swd[(ci*9 + k)*8 + c] = dup(w[co0+c][ci][k])
    for (int i = tid; i < CIN * 9 * CO_T; i += 256) {
        int c   = i & 7;
        int kci = i >> 3;
        int ci  = kci / 9;
        int k   = kci - ci * 9;
        float w = wgt[((co0 + c) * CIN + ci) * 9 + k];
        swd[i] = pack2(w, w);
    }
    __syncthreads();     // the ONLY block barrier

    const int  h    = h0 + ty;                 // output row
    const bool v0   = (h - 1 >= 0);
    const bool v2   = (h + 1 < HH);
    const bool lEdge = (tx == 0),  lVal = (w0 > 0);
    const bool rEdge = (tx == 15), rVal = (w0 + WT < WW);

    const float* p0 = x + (h - 1) * WW + w0 + tx * 4;
    const float* p1 = x + (h    ) * WW + w0 + tx * 4;
    const float* p2 = x + (h + 1) * WW + w0 + tx * 4;

    unsigned long long acc[CO_T][2];
#pragma unroll
    for (int c = 0; c < CO_T; c++) { acc[c][0] = 0ull; acc[c][1] = 0ull; }

    const unsigned long long* wci = swd;

    for (int ci = 0; ci < CIN; ci++) {
#pragma unroll
        for (int kh = 0; kh < 3; kh++) {
            const float* rp = (kh == 0) ? p0 : (kh == 1) ? p1 : p2;
            const bool   hv = (kh == 0) ? v0 : (kh == 1) ? true : v2;

            float4 a4 = hv ? *(const float4*)rp
                           : make_float4(0.f, 0.f, 0.f, 0.f);
            float lft = __shfl_up_sync  (0xffffffffu, a4.w, 1);
            float rgt = __shfl_down_sync(0xffffffffu, a4.x, 1);
            if (lEdge) lft = (hv && lVal) ? rp[-1] : 0.f;
            if (rEdge) rgt = (hv && rVal) ? rp[4]  : 0.f;

            unsigned long long xp[5];
            xp[0] = pack2(lft,  a4.x);
            xp[1] = pack2(a4.x, a4.y);
            xp[2] = pack2(a4.y, a4.z);
            xp[3] = pack2(a4.z, a4.w);
            xp[4] = pack2(a4.w, rgt);

#pragma unroll
            for (int kw = 0; kw < 3; kw++) {
                const unsigned long long* wk = wci + (kh * 3 + kw) * CO_T;
#pragma unroll
                for (int cp = 0; cp < CO_T; cp += 2) {
                    ulonglong2 w2 = *(const ulonglong2*)(wk + cp);   // LDS.128 bcast
                    fma2(acc[cp][0],     xp[kw],     w2.x);
                    fma2(acc[cp][1],     xp[kw + 2], w2.x);
                    fma2(acc[cp + 1][0], xp[kw],     w2.y);
                    fma2(acc[cp + 1][1], xp[kw + 2], w2.y);
                }
            }
        }
        p0 += HH * WW; p1 += HH * WW; p2 += HH * WW;
        wci += 9 * CO_T;
    }

#pragma unroll
    for (int c = 0; c < CO_T; c++) {
        float bv = bias[co0 + c];
        float q0, q1, q2, q3;
        unpack2(acc[c][0], q0, q1);
        unpack2(acc[c][1], q2, q3);
        float* orow = &d_y[((co0 + c) * HH + h) * WW + w0 + tx * 4];
        *(float4*)orow = make_float4(q0 + bv, q1 + bv, q2 + bv, q3 + bv);
    }
}

// ===========================================================================
// Register-resident 512-pt FFT (unchanged core)
// ===========================================================================
template<int INV>
__device__ __forceinline__ void fft16_reg(float2 v[16])
{
    float2 t;
    t = v[1];  v[1]  = v[8];  v[8]  = t;
    t = v[2];  v[2]  = v[4];  v[4]  = t;
    t = v[3];  v[3]  = v[12]; v[12] = t;
    t = v[5];  v[5]  = v[10]; v[10] = t;
    t = v[7];  v[7]  = v[14]; v[14] = t;
    t = v[11]; v[11] = v[13]; v[13] = t;

    const float CC[8] = { 1.f,  0.92387953251128674f,  0.70710678118654752f,
                          0.38268343236508977f, 0.f, -0.38268343236508977f,
                         -0.70710678118654752f, -0.92387953251128674f };
    const float SS[8] = { 0.f,  0.38268343236508977f,  0.70710678118654752f,
                          0.92387953251128674f, 1.f,  0.92387953251128674f,
                          0.70710678118654752f,  0.38268343236508977f };
#pragma unroll
    for (int st = 1; st <= 4; st++) {
        const int half = 1 << (st - 1);
#pragma unroll
        for (int j = 0; j < 8; j++) {
            const int pos = j & (half - 1);
            const int i0  = ((j >> (st - 1)) << st) | pos;
            const int i1  = i0 + half;
            const int tj  = pos << (4 - st);
            const float wr = CC[tj];
            const float wi = INV ? SS[tj] : -SS[tj];
            float br = v[i1].x * wr - v[i1].y * wi;
            float bi = v[i1].x * wi + v[i1].y * wr;
            v[i1].x = v[i0].x - br; v[i1].y = v[i0].y - bi;
            v[i0].x += br;          v[i0].y += bi;
        }
    }
}

template<int INV>
__device__ __forceinline__ void fft32_xlane(float2 v[16], int lane)
{
    const unsigned m = 0xffffffffu;
    int rl = __brev(lane) >> 27;
#pragma unroll
    for (int r = 0; r < 16; r++) {
        v[r].x = __shfl_sync(m, v[r].x, rl);
        v[r].y = __shfl_sync(m, v[r].y, rl);
    }
#pragma unroll
    for (int st = 1; st <= 5; st++) {
        const int half = 1 << (st - 1);
        float ang = (INV ? 3.14159265358979323f : -3.14159265358979323f)
                    * (float)(lane & (half - 1)) / (float)half;
        float wi, wr;
        __sincosf(ang, &wi, &wr);
        const float sgn = (lane & half) ? -1.f : 1.f;
        const bool hi = (lane & half) != 0;
#pragma unroll
        for (int r = 0; r < 16; r++) {
            float px = __shfl_xor_sync(m, v[r].x, half);
            float py = __shfl_xor_sync(m, v[r].y, half);
            float bx = hi ? v[r].x : px;
            float by = hi ? v[r].y : py;
            float ax = hi ? px : v[r].x;
            float ay = hi ? py : v[r].y;
            float tx = bx * wr - by * wi;
            float ty = bx * wi + by * wr;
            v[r].x = fmaf(sgn, tx, ax);
            v[r].y = fmaf(sgn, ty, ay);
        }
    }
}

template<int INV>
__device__ __forceinline__ void twiddle512(float2 v[16], int lane)
{
    float ang = (INV ? 6.28318530717958648f : -6.28318530717958648f)
                * (float)lane / 512.f;
    float s, c;
    __sincosf(ang, &s, &c);
    float wr = 1.f, wi = 0.f;
#pragma unroll
    for (int r = 1; r < 16; r++) {
        float nwr = wr * c - wi * s;
        float nwi = wr * s + wi * c;
        wr = nwr; wi = nwi;
        float xr = v[r].x, xi = v[r].y;
        v[r].x = xr * wr - xi * wi;
        v[r].y = xr * wi + xi * wr;
    }
}

__device__ __forceinline__ void fft512_fwd(float2 v[16], int lane)
{
    fft16_reg<0>(v);
    twiddle512<0>(v, lane);
    fft32_xlane<0>(v, lane);
}
__device__ __forceinline__ void fft512_inv(float2 v[16], int lane)
{
    fft32_xlane<1>(v, lane);
    twiddle512<1>(v, lane);
    fft16_reg<1>(v);
}

__device__ __forceinline__ int swz(int idx) { return idx ^ ((idx >> 7) & 15); }
__device__ __forceinline__ int padz(int i) { return i + (i >> 4); }
__device__ __forceinline__ int padm(int i) { return i + (i >> 5); }

// ===========================================================================
// Pass 1: column FFT of packed pair z = y[2p] + i*y[2p+1].
// ===========================================================================
__global__ __launch_bounds__(256) void fft_cols_fwd2()
{
    __shared__ char raw[36864];
    float2* sIn  = (float2*)raw;
    float2* sOut = (float2*)raw;

    const int tid  = threadIdx.x;
    const int lane = tid & 31;
    const int wp   = tid >> 5;
    const int p    = blockIdx.y;
    const int w0   = blockIdx.x * 8;

    const float* y1 = &d_y[(2 * p)     * HH * WW];
    const float* y2 = &d_y[(2 * p + 1) * HH * WW];
    for (int i = tid; i < 4096; i += 256) {
        int h = i >> 3, c = i & 7;
        int g = h * WW + w0 + c;
        sIn[h * 9 + c] = make_float2(y1[g], y2[g]);
    }
    __syncthreads();

    float2 v[16];
#pragma unroll
    for (int r = 0; r < 16; r++)
        v[r] = sIn[(lane + 32 * r) * 9 + wp];
    __syncthreads();

    fft512_fwd(v, lane);

#pragma unroll
    for (int r = 0; r < 16; r++) {
        int k = r + 16 * lane;
        sOut[swz((k << 3) | wp)] = v[r];
    }
    __syncthreads();

    for (int i = tid; i < 4096; i += 256) {
        int k = i >> 3, c = i & 7;
        d_spec[(p * HH + k) * WW + w0 + c] = sOut[swz(i)];
    }
}

// ===========================================================================
// Pass 2: Hermitian-split row pass (unchanged).
// ===========================================================================
__global__ __launch_bounds__(128) void fft_rows_mask2(const float* __restrict__ mask)
{
    __shared__ float2 zbuf[2][2][544];
    __shared__ float  mbuf[2][4][528];

    const int tid   = threadIdx.x;
    const int lane  = tid & 31;
    const int wp    = tid >> 5;
    const int slot  = wp >> 1;
    const int role  = wp & 1;
    const int p     = blockIdx.y;
    const int k1    = blockIdx.x * 2 + slot;
    const bool act  = (k1 <= 256);

    const int rowA  = k1;
    const int rowB  = (512 - k1) & 511;
    const int myrow = role ? rowB : rowA;

    float2 v[16];
    if (act) {
        const float2* srow = &d_spec[(p * HH + myrow) * WW];
#pragma unroll
        for (int r = 0; r < 16; r++)
            v[r] = srow[lane + 32 * r];

        const float* m1 = &mask[((2 * p)     * HH + myrow) * WW];
        const float* m2 = &mask[((2 * p + 1) * HH + myrow) * WW];
        float* d1 = mbuf[slot][role];
        float* d2 = mbuf[slot][2 + role];
#pragma unroll
        for (int t = 0; t < 16; t++) {
            int i = lane + 32 * t;
            d1[padm(i)] = m1[i];
            d2[padm(i)] = m2[i];
        }

        fft512_fwd(v, lane);

        float2* zme = zbuf[slot][role];
#pragma unroll
        for (int r = 0; r < 16; r++) {
            int k = r + 16 * lane;
            zme[padz(k)] = v[r];
        }
    }
    __syncthreads();

    if (act) {
        const float c4 = 0.25f / (512.0f * 512.0f);
        const float* m1A = mbuf[slot][0];
        const float* m1B = mbuf[slot][1];
        const float* m2A = mbuf[slot][2];
        const float* m2B = mbuf[slot][3];
        const float2* zA = zbuf[slot][0];
        const float2* zB = zbuf[slot][1];

#pragma unroll
        for (int r = 0; r < 16; r++) {
            int k  = r + 16 * lane;
            int r2 = (512 - k) & 511;
            if (role == 0) {
                float2 zb = zB[padz(r2)];
                float sx = v[r].x + zb.x, sy = v[r].y - zb.y;
                float dx = v[r].x - zb.x, dy = v[r].y + zb.y;
                float m1v = (m1A[padm(k)] + m1B[padm(r2)]) * c4;
                float m2v = (m2A[padm(k)] + m2B[padm(r2)]) * c4;
                v[r] = make_float2(m1v * sx + m2v * dx, m1v * sy + m2v * dy);
            } else {
                float2 za = zA[padz(r2)];
                float sx = za.x + v[r].x, sy = za.y - v[r].y;
                float dx = za.x - v[r].x, dy = za.y + v[r].y;
                float m1v = (m1A[padm(r2)] + m1B[padm(k)]) * c4;
                float m2v = (m2A[padm(r2)] + m2B[padm(k)]) * c4;
                v[r] = make_float2(m1v * sx - m2v * dx, -m1v * sy + m2v * dy);
            }
        }

        fft512_inv(v, lane);

        if (!(role == 1 && rowB == rowA)) {
            float2* orow = &d_spec[(p * HH + myrow) * WW];
#pragma unroll
            for (int r = 0; r < 16; r++)
                orow[lane + 32 * r] = v[r];
        }
    }
}

// ===========================================================================
// Pass 3: inverse column FFT; Re -> channel 2p, Im -> channel 2p+1.
// ===========================================================================
__global__ __launch_bounds__(256) void fft_cols_inv2(float* __restrict__ out)
{
    __shared__ char raw[36864];
    float2* sIn  = (float2*)raw;
    float2* sOut = (float2*)raw;

    const int tid  = threadIdx.x;
    const int lane = tid & 31;
    const int wp   = tid >> 5;
    const int p    = blockIdx.y;
    const int w0   = blockIdx.x * 8;

    for (int i = tid; i < 4096; i += 256) {
        int k = i >> 3, c = i & 7;
        sIn[swz(i)] = d_spec[(p * HH + k) * WW + w0 + c];
    }
    __syncthreads();

    float2 v[16];
#pragma unroll
    for (int r = 0; r < 16; r++) {
        int k = r + 16 * lane;
        v[r] = sIn[swz((k << 3) | wp)];
    }
    __syncthreads();

    fft512_inv(v, lane);

#pragma unroll
    for (int r = 0; r < 16; r++)
        sOut[(lane + 32 * r) * 9 + wp] = v[r];
    __syncthreads();

    float* o1 = &out[(2 * p)     * HH * WW];
    float* o2 = &out[(2 * p + 1) * HH * WW];
    for (int i = tid; i < 4096; i += 256) {
        int hh = i >> 3, c = i & 7;
        float2 s = sOut[hh * 9 + c];
        int g = hh * WW + w0 + c;
        o1[g] = s.x;
        o2[g] = s.y;
    }
}

// ===========================================================================
extern "C" void kernel_launch(void* const* d_in, const int* in_sizes, int n_in,
                              void* d_out, int out_size)
{
    const float* x    = (const float*)d_in[0];   // (64,512,512)
    const float* wgt  = (const float*)d_in[1];   // (128,64,3,3)
    const float* bias = (const float*)d_in[2];   // (128,)
    const float* mask = (const float*)d_in[3];   // (128,512,512)
    float* out = (float*)d_out;                  // (128,512,512)

    conv3x3_kernel<<<dim3(WW / WT, HH / HT, COUT / CO_T), 256>>>(x, wgt, bias);
    fft_cols_fwd2 <<<dim3(WW / 8, COUT / 2), 256>>>();
    fft_rows_mask2<<<dim3(129, COUT / 2), 128>>>(mask);
    fft_cols_inv2 <<<dim3(WW / 8, COUT / 2), 256>>>(out);
}